// round 16
// baseline (speedup 1.0000x reference)
#include <cuda_runtime.h>
#include <cuda_bf16.h>
#include <cstdint>

#define B_    16
#define S_    16
#define D_    4096
#define H_    32
#define KVH_  8
#define HD_   128
#define NREP_ 4
#define MAXS_ 4096
#define MROWS 256
#define KS    4
#define NC    6144

__device__ float  g_q  [MROWS * D_];
__device__ float  g_kn [MROWS * KVH_ * HD_];
__device__ float  g_vn [MROWS * KVH_ * HD_];
__device__ float  g_ctx[MROWS * D_];
__device__ float  g_p  [KS][MROWS * NC];
__device__ float2 g_tab[S_ * 64];

__device__ __forceinline__ void mma16h(float* d, unsigned a0, unsigned a1, unsigned a2,
                                       unsigned a3, unsigned b0, unsigned b1) {
    asm volatile(
        "mma.sync.aligned.m16n8k16.row.col.f32.f16.f16.f32 "
        "{%0,%1,%2,%3}, {%4,%5,%6,%7}, {%8,%9}, {%0,%1,%2,%3};"
        : "+f"(d[0]), "+f"(d[1]), "+f"(d[2]), "+f"(d[3])
        : "r"(a0), "r"(a1), "r"(a2), "r"(a3), "r"(b0), "r"(b1));
}
__device__ __forceinline__ void ldsm4(unsigned& r0, unsigned& r1, unsigned& r2,
                                      unsigned& r3, unsigned addr) {
    asm volatile("ldmatrix.sync.aligned.m8n8.x4.shared.b16 {%0,%1,%2,%3}, [%4];"
                 : "=r"(r0), "=r"(r1), "=r"(r2), "=r"(r3) : "r"(addr));
}
__device__ __forceinline__ void ldsm4t(unsigned& r0, unsigned& r1, unsigned& r2,
                                       unsigned& r3, unsigned addr) {
    asm volatile("ldmatrix.sync.aligned.m8n8.x4.trans.shared.b16 {%0,%1,%2,%3}, [%4];"
                 : "=r"(r0), "=r"(r1), "=r"(r2), "=r"(r3) : "r"(addr));
}
__device__ __forceinline__ float ex2f(float x) {
    float r; asm("ex2.approx.f32 %0, %1;" : "=f"(r) : "f"(x)); return r;
}
__device__ __forceinline__ unsigned packh2(float lo, float hi) {
    unsigned d; asm("cvt.rn.f16x2.f32 %0, %1, %2;" : "=r"(d) : "f"(hi), "f"(lo)); return d;
}
#define GROUP_BAR(id) asm volatile("bar.sync %0, 128;" :: "r"(id) : "memory")

// ======================= rope table =======================
__global__ void rope_tab_kernel(const int* __restrict__ sp) {
    int idx = threadIdx.x;
    int s = idx >> 6, pp = idx & 63;
    double f = (double)(sp[0] + s) * exp(-9.210340371976184 * ((double)pp / 64.0));
    double cd, sd; sincos(f, &sd, &cd);
    g_tab[idx] = make_float2((float)cd, (float)sd);
}

// ======================= fp16 GEMM 128x128, K-split, double-buffered =======================
#define BK  32
#define GAW 20
#define GBW 68
#define GASZ (128*GAW)
#define GBSZ (32*GBW)
#define G16_SMEM_BYTES ((2*GASZ + 2*GBSZ) * 4)

__device__ void gemm16_tile(const float* __restrict__ A, int lda,
                            const float* __restrict__ W, int ldw,
                            float* __restrict__ C, int ldc,
                            int m0, int n0w, int n0c, int kbase, int KT)
{
    extern __shared__ float sm[];
    unsigned* AhB[2] = { (unsigned*)sm, (unsigned*)sm + GASZ };
    unsigned* BhB[2] = { (unsigned*)sm + 2 * GASZ, (unsigned*)sm + 2 * GASZ + GBSZ };

    int tid = threadIdx.x, lane = tid & 31, wid = tid >> 5;
    int wm = wid >> 2, wn = wid & 3;
    int gr = lane >> 2, kq = lane & 3;

    int arow = tid >> 1, ahalf = tid & 1;
    int brow = tid >> 3, bslot = tid & 7;

    unsigned sbase = (unsigned)__cvta_generic_to_shared(sm);
    unsigned a_addr0 = sbase + (unsigned)(wm * 64 + (lane & 15)) * (GAW * 4) +
                       ((lane >> 4) << 4);
    unsigned b_addr0 = sbase + (unsigned)(2 * GASZ) * 4 +
                       (unsigned)((lane & 7) + (((lane >> 3) & 1) << 3)) * (GBW * 4) +
                       (unsigned)(wn * 64) + ((lane >> 4) << 4);

    float acc[4][4][4];
#pragma unroll
    for (int mt = 0; mt < 4; mt++)
#pragma unroll
        for (int nt = 0; nt < 4; nt++)
#pragma unroll
            for (int i = 0; i < 4; i++) acc[mt][nt][i] = 0.f;

    unsigned pa[8], pb[8];
    auto prefetch = [&](int k0) {
        const float4* ap = (const float4*)(A + (long)(m0 + arow) * lda + k0 + ahalf * 16);
        const float4* bp = (const float4*)(W + (long)(k0 + brow) * ldw + n0w + bslot * 16);
#pragma unroll
        for (int i = 0; i < 4; i++) {
            float4 av = ap[i];
            float4 bv = bp[i];
            pa[2 * i]     = packh2(av.x, av.y);
            pa[2 * i + 1] = packh2(av.z, av.w);
            pb[2 * i]     = packh2(bv.x, bv.y);
            pb[2 * i + 1] = packh2(bv.z, bv.w);
        }
    };
    auto store_tile = [&](int buf) {
        unsigned* Ah = AhB[buf];
        unsigned* Bh = BhB[buf];
        *(uint4*)&Ah[arow * GAW + ahalf * 8]     = make_uint4(pa[0], pa[1], pa[2], pa[3]);
        *(uint4*)&Ah[arow * GAW + ahalf * 8 + 4] = make_uint4(pa[4], pa[5], pa[6], pa[7]);
        *(uint4*)&Bh[brow * GBW + bslot * 8]     = make_uint4(pb[0], pb[1], pb[2], pb[3]);
        *(uint4*)&Bh[brow * GBW + bslot * 8 + 4] = make_uint4(pb[4], pb[5], pb[6], pb[7]);
    };

    prefetch(kbase);
    store_tile(0);
    prefetch(kbase + BK);
    __syncthreads();

    for (int kt = 0; kt < KT; kt++) {
        if (kt + 1 < KT) store_tile((kt + 1) & 1);       // other buffer: no conflict
        if (kt + 2 < KT) prefetch(kbase + (kt + 2) * BK);

        unsigned aoff = (kt & 1) ? (unsigned)(GASZ * 4) : 0u;
        unsigned boff = (kt & 1) ? (unsigned)(GBSZ * 4) : 0u;
#pragma unroll
        for (int kb = 0; kb < 2; kb++) {
            unsigned af[4][4];
#pragma unroll
            for (int mt = 0; mt < 4; mt++)
                ldsm4(af[mt][0], af[mt][1], af[mt][2], af[mt][3],
                      a_addr0 + aoff + (unsigned)(mt * 16 * GAW * 4) + kb * 32);
#pragma unroll
            for (int ntp = 0; ntp < 2; ntp++) {
                unsigned b00, b01, b10, b11;
                ldsm4t(b00, b01, b10, b11,
                       b_addr0 + boff + (unsigned)(kb * 16 * GBW * 4) + ntp * 32);
#pragma unroll
                for (int mt = 0; mt < 4; mt++) {
                    mma16h(acc[mt][2 * ntp],     af[mt][0], af[mt][1], af[mt][2], af[mt][3], b00, b01);
                    mma16h(acc[mt][2 * ntp + 1], af[mt][0], af[mt][1], af[mt][2], af[mt][3], b10, b11);
                }
            }
        }
        __syncthreads();
    }

#pragma unroll
    for (int mt = 0; mt < 4; mt++)
#pragma unroll
        for (int nt = 0; nt < 4; nt++) {
            int row = m0 + wm * 64 + mt * 16 + gr;
            int col = n0c + wn * 32 + nt * 8 + 2 * kq;
            *(float2*)(C + (long)row * ldc + col) =
                make_float2(acc[mt][nt][0], acc[mt][nt][1]);
            *(float2*)(C + (long)(row + 8) * ldc + col) =
                make_float2(acc[mt][nt][2], acc[mt][nt][3]);
        }
}

__global__ void __launch_bounds__(256, 2)
qkv_kernel(const float* __restrict__ x, const float* __restrict__ Wq,
           const float* __restrict__ Wk, const float* __restrict__ Wv) {
    int y = blockIdx.y, z = blockIdx.z;
    const float* W; int ldw, n0w, n0c;
    if (y < 32)      { W = Wq; ldw = 4096; n0w = y * 128;        n0c = y * 128; }
    else if (y < 40) { W = Wk; ldw = 1024; n0w = (y - 32) * 128; n0c = 4096 + (y - 32) * 128; }
    else             { W = Wv; ldw = 1024; n0w = (y - 40) * 128; n0c = 5120 + (y - 40) * 128; }
    gemm16_tile(x, 4096, W, ldw, g_p[z], NC, blockIdx.x * 128, n0w, n0c, z * 1024, 32);
}

__global__ void __launch_bounds__(256, 2)
out_kernel(const float* __restrict__ Wo) {
    int z = blockIdx.z;
    gemm16_tile(g_ctx, 4096, Wo, 4096, g_p[z], 4096,
                blockIdx.x * 128, blockIdx.y * 128, blockIdx.y * 128, z * 1024, 32);
}

// ======================= combines =======================
__global__ void qkv_combine_kernel() {
    int idx = blockIdx.x * 256 + threadIdx.x;
    int row = idx / (NC / 2);
    int p   = idx - row * (NC / 2);
    int col = 2 * p;
    float v0 = 0.f, v1 = 0.f;
#pragma unroll
    for (int h = 0; h < KS; h++) {
        const float* src = g_p[h] + (long)row * NC + col;
        v0 += src[0]; v1 += src[1];
    }
    if (col < 4096) {
        int pp = (col & 127) >> 1;
        float2 cs = g_tab[((row & 15) << 6) + pp];
        const float qs = 0.08838834764831845f * 1.4426950408889634f;
        float t = (v0 * cs.x - v1 * cs.y) * qs;
        v1 = (v0 * cs.y + v1 * cs.x) * qs; v0 = t;
        *(float2*)(g_q + (long)row * 4096 + col) = make_float2(v0, v1);
    } else if (col < 5120) {
        int c2 = col - 4096;
        int pp = (c2 & 127) >> 1;
        float2 cs = g_tab[((row & 15) << 6) + pp];
        float t = v0 * cs.x - v1 * cs.y;
        v1 = v0 * cs.y + v1 * cs.x; v0 = t;
        *(float2*)(g_kn + (long)row * 1024 + c2) = make_float2(v0, v1);
    } else {
        *(float2*)(g_vn + (long)row * 1024 + (col - 5120)) = make_float2(v0, v1);
    }
}

__global__ void out_combine_kernel(float* __restrict__ out) {
    int idx = blockIdx.x * 256 + threadIdx.x;
    float4 a = *(const float4*)(g_p[0] + 4 * (long)idx);
    float4 b = *(const float4*)(g_p[1] + 4 * (long)idx);
    float4 c = *(const float4*)(g_p[2] + 4 * (long)idx);
    float4 d = *(const float4*)(g_p[3] + 4 * (long)idx);
    *(float4*)(out + 4 * (long)idx) =
        make_float4(a.x + b.x + c.x + d.x, a.y + b.y + c.y + d.y,
                    a.z + b.z + c.z + d.z, a.w + b.w + c.w + d.w);
}

// ======================= attention: double-buffered Kh/Vh, 1 barrier/chunk =======================
#define TC   64
#define SSTR 132
#define KW   68
#define VW   68
#define QW   68
#define KHSZ (TC*KW)
#define VHSZ (TC*VW)
#define AOFF_KH0 0
#define AOFF_KH1 KHSZ
#define AOFF_VH0 (2*KHSZ)
#define AOFF_VH1 (2*KHSZ + VHSZ)
#define AOFF_QH  (2*KHSZ + 2*VHSZ)
#define OBS      (TC*SSTR)
#define AOFF_EX  (4*OBS)
#define ATTN_SMEM_BYTES ((AOFF_EX + 512) * 4)

__global__ void __launch_bounds__(512, 1)
attn_kernel(const float* __restrict__ cache_k,
            const float* __restrict__ cache_v,
            const int* __restrict__ sp)
{
    extern __shared__ float sm[];
    unsigned* KhB[2] = { (unsigned*)(sm + AOFF_KH0), (unsigned*)(sm + AOFF_KH1) };
    unsigned* VhB[2] = { (unsigned*)(sm + AOFF_VH0), (unsigned*)(sm + AOFF_VH1) };
    unsigned* Qh = (unsigned*)(sm + AOFF_QH);
    float* ex = sm + AOFF_EX;

    int tid = threadIdx.x, lane = tid & 31, wid = tid >> 5;
    int b = blockIdx.x >> 3, kvh = blockIdx.x & 7;
    int start = sp[0], kvlen = start + S_;
    int wm = wid & 3, wn = wid >> 2;
    int gr = lane >> 2, kq = lane & 3;
    int rm = wm * 16;
    int gtid = wm * 32 + lane;

    int tok  = wn * 16 + (gtid >> 3);
    int slot = gtid & 7;

    unsigned sbase = (unsigned)__cvta_generic_to_shared(sm);
    unsigned qa_addr = sbase + AOFF_QH * 4 +
        (unsigned)(rm + (lane & 15)) * (QW * 4) + ((lane >> 4) << 4);
    unsigned kb_addr0 = sbase + AOFF_KH0 * 4 +
        (unsigned)(wn * 16 + (lane & 7) + ((lane >> 4) << 3)) * (KW * 4) +
        (((lane >> 3) & 1) << 4);
    unsigned vb_addr0 = sbase + AOFF_VH0 * 4 +
        (unsigned)(wn * 16 + (lane & 7) + (((lane >> 3) & 1) << 3)) * (VW * 4) +
        ((lane >> 4) << 4);

    {
        int r = tid >> 3, sl = tid & 7;
        const float* qp = g_q + (long)(b * S_ + (r & 15)) * D_ + (kvh * NREP_ + (r >> 4)) * HD_;
#pragma unroll
        for (int i = 0; i < 8; i++) {
            int w = sl + 8 * i;
            float2 v = *(const float2*)(qp + 2 * w);
            Qh[r * QW + w] = packh2(v.x, v.y);
        }
    }

    float m0r = -1e30f, m1r = -1e30f, l0r = 0.f, l1r = 0.f;
    float cacc[16][4];
#pragma unroll
    for (int nt = 0; nt < 16; nt++)
#pragma unroll
        for (int i = 0; i < 4; i++) cacc[nt][i] = 0.f;

    unsigned kh[8], vh[8];
    auto prefetch = [&](int t0) {
        int t = t0 + tok;
        const float *sk, *sv;
        if (t < start) {
            long o = ((((long)b * MAXS_ + t) * KVH_) + kvh) * HD_;
            sk = cache_k + o; sv = cache_v + o;
        } else {
            int tt = min(t, kvlen - 1);
            long o = (((long)(b * S_ + (tt - start))) * KVH_ + kvh) * HD_;
            sk = g_kn + o; sv = g_vn + o;
        }
        const float4* k4 = (const float4*)(sk + slot * 16);
        const float4* v4 = (const float4*)(sv + slot * 16);
#pragma unroll
        for (int i = 0; i < 4; i++) {
            float4 kv = k4[i];
            float4 vv = v4[i];
            kh[2 * i]     = packh2(kv.x, kv.y);
            kh[2 * i + 1] = packh2(kv.z, kv.w);
            vh[2 * i]     = packh2(vv.x, vv.y);
            vh[2 * i + 1] = packh2(vv.z, vv.w);
        }
    };
    auto store_tile = [&](int buf) {
        unsigned* Kh = KhB[buf];
        unsigned* Vh = VhB[buf];
        *(uint4*)&Kh[tok * KW + slot * 8]     = make_uint4(kh[0], kh[1], kh[2], kh[3]);
        *(uint4*)&Kh[tok * KW + slot * 8 + 4] = make_uint4(kh[4], kh[5], kh[6], kh[7]);
        *(uint4*)&Vh[tok * VW + slot * 8]     = make_uint4(vh[0], vh[1], vh[2], vh[3]);
        *(uint4*)&Vh[tok * VW + slot * 8 + 4] = make_uint4(vh[4], vh[5], vh[6], vh[7]);
    };

    int NCH = (kvlen + TC - 1) / TC;
    prefetch(0);
    store_tile(0);
    prefetch(TC);
    __syncthreads();     // Qh + buf0 visible CTA-wide

    for (int j = 0; j < NCH; j++) {
        if (j + 1 < NCH) store_tile((j + 1) & 1);   // other buffer: overlaps compute
        if (j + 2 < NCH) prefetch((j + 2) * TC);

        unsigned koff = (j & 1) ? (unsigned)(KHSZ * 4) : 0u;
        unsigned voff = (j & 1) ? (unsigned)(VHSZ * 4) : 0u;

        // ---- S = Q K^T over own 16 tokens ----
        float sacc[2][4];
#pragma unroll
        for (int nt = 0; nt < 2; nt++)
#pragma unroll
            for (int i = 0; i < 4; i++) sacc[nt][i] = 0.f;
#pragma unroll
        for (int kb = 0; kb < 8; kb++) {
            unsigned a0, a1, a2, a3, b0, b1, b2, b3;
            ldsm4(a0, a1, a2, a3, qa_addr + kb * 32);
            ldsm4(b0, b1, b2, b3, kb_addr0 + koff + kb * 32);
            mma16h(sacc[0], a0, a1, a2, a3, b0, b1);
            mma16h(sacc[1], a0, a1, a2, a3, b2, b3);
        }

        if (j == NCH - 1 && (kvlen & (TC - 1))) {   // never for kvlen=4096
#pragma unroll
            for (int nt = 0; nt < 2; nt++) {
                int tk = j * TC + wn * 16 + nt * 8 + 2 * kq;
                if (tk >= kvlen)     { sacc[nt][0] = -1e30f; sacc[nt][2] = -1e30f; }
                if (tk + 1 >= kvlen) { sacc[nt][1] = -1e30f; sacc[nt][3] = -1e30f; }
            }
        }

        // ---- warp-local online softmax ----
        float mw0 = fmaxf(fmaxf(sacc[0][0], sacc[0][1]), fmaxf(sacc[1][0], sacc[1][1]));
        float mw1 = fmaxf(fmaxf(sacc[0][2], sacc[0][3]), fmaxf(sacc[1][2], sacc[1][3]));
        mw0 = fmaxf(mw0, __shfl_xor_sync(0xffffffffu, mw0, 1));
        mw0 = fmaxf(mw0, __shfl_xor_sync(0xffffffffu, mw0, 2));
        mw1 = fmaxf(mw1, __shfl_xor_sync(0xffffffffu, mw1, 1));
        mw1 = fmaxf(mw1, __shfl_xor_sync(0xffffffffu, mw1, 2));
        float M0 = fmaxf(m0r, mw0), M1 = fmaxf(m1r, mw1);
        if (__any_sync(0xffffffffu, (M0 > m0r) | (M1 > m1r))) {
            float sc0 = ex2f(m0r - M0), sc1 = ex2f(m1r - M1);
            l0r *= sc0;  l1r *= sc1;
#pragma unroll
            for (int nt = 0; nt < 16; nt++) {
                cacc[nt][0] *= sc0; cacc[nt][1] *= sc0;
                cacc[nt][2] *= sc1; cacc[nt][3] *= sc1;
            }
            m0r = M0;  m1r = M1;
        }
        float Mb0 = M0 - 8.f, Mb1 = M1 - 8.f;
        float g00 = ex2f(sacc[0][0] - Mb0), g01 = ex2f(sacc[0][1] - Mb0);
        float g02 = ex2f(sacc[0][2] - Mb1), g03 = ex2f(sacc[0][3] - Mb1);
        float h00 = ex2f(sacc[1][0] - Mb0), h01 = ex2f(sacc[1][1] - Mb0);
        float h02 = ex2f(sacc[1][2] - Mb1), h03 = ex2f(sacc[1][3] - Mb1);
        l0r += (g00 + g01) + (h00 + h01);
        l1r += (g02 + g03) + (h02 + h03);
        unsigned pa0 = packh2(g00, g01), pa1 = packh2(g02, g03);
        unsigned pa2 = packh2(h00, h01), pa3 = packh2(h02, h03);

        // ---- O += P V over own 16 tokens x 128 dims ----
#pragma unroll
        for (int db = 0; db < 8; db++) {
            unsigned b00, b01, b10, b11;
            ldsm4t(b00, b01, b10, b11, vb_addr0 + voff + db * 32);
            mma16h(cacc[2 * db],     pa0, pa1, pa2, pa3, b00, b01);
            mma16h(cacc[2 * db + 1], pa0, pa1, pa2, pa3, b10, b11);
        }

        GROUP_BAR(1 + wn);   // buf j reads done group-wide; buf j+1 stores visible
    }

    // ---- epilogue: exact merge of the 4 group-partials ----
    l0r += __shfl_xor_sync(0xffffffffu, l0r, 1);
    l0r += __shfl_xor_sync(0xffffffffu, l0r, 2);
    l1r += __shfl_xor_sync(0xffffffffu, l1r, 1);
    l1r += __shfl_xor_sync(0xffffffffu, l1r, 2);
    if (kq == 0) { ex[wn * 64 + rm + gr] = m0r; ex[wn * 64 + rm + gr + 8] = m1r; }
    __syncthreads();
    float M0 = -1e30f, M1 = -1e30f;
#pragma unroll
    for (int w = 0; w < 4; w++) {
        M0 = fmaxf(M0, ex[w * 64 + rm + gr]);
        M1 = fmaxf(M1, ex[w * 64 + rm + gr + 8]);
    }
    float sc0 = ex2f(m0r - M0), sc1 = ex2f(m1r - M1);
    if (kq == 0) {
        ex[256 + wn * 64 + rm + gr]     = l0r * sc0;
        ex[256 + wn * 64 + rm + gr + 8] = l1r * sc1;
    }
    float* Ob = sm + wn * OBS;
#pragma unroll
    for (int nt = 0; nt < 16; nt++) {
        int d = nt * 8 + 2 * kq;
        *(float2*)&Ob[(rm + gr) * SSTR + d] =
            make_float2(cacc[nt][0] * sc0, cacc[nt][1] * sc0);
        *(float2*)&Ob[(rm + gr + 8) * SSTR + d] =
            make_float2(cacc[nt][2] * sc1, cacc[nt][3] * sc1);
    }
    __syncthreads();
#pragma unroll
    for (int i = 0; i < 4; i++) {
        int f = i * 512 + tid;
        int r = f >> 5, d4 = f & 31;
        float4 s0 = *(const float4*)&sm[0 * OBS + r * SSTR + d4 * 4];
        float4 s1 = *(const float4*)&sm[1 * OBS + r * SSTR + d4 * 4];
        float4 s2 = *(const float4*)&sm[2 * OBS + r * SSTR + d4 * 4];
        float4 s3 = *(const float4*)&sm[3 * OBS + r * SSTR + d4 * 4];
        float L = ex[256 + r] + ex[256 + 64 + r] + ex[256 + 128 + r] + ex[256 + 192 + r];
        float inv = 1.f / L;
        float4 o = make_float4((s0.x + s1.x + s2.x + s3.x) * inv,
                               (s0.y + s1.y + s2.y + s3.y) * inv,
                               (s0.z + s1.z + s2.z + s3.z) * inv,
                               (s0.w + s1.w + s2.w + s3.w) * inv);
        *(float4*)(g_ctx + (long)(b * S_ + (r & 15)) * D_ +
                   (kvh * NREP_ + (r >> 4)) * HD_ + d4 * 4) = o;
    }
}

// ======================= launch =======================
extern "C" void kernel_launch(void* const* d_in, const int* in_sizes, int n_in,
                              void* d_out, int out_size) {
    const float* x       = (const float*)d_in[0];
    const float* Wq      = (const float*)d_in[1];
    const float* Wk      = (const float*)d_in[2];
    const float* Wv      = (const float*)d_in[3];
    const float* Wo      = (const float*)d_in[4];
    const float* cache_k = (const float*)d_in[5];
    const float* cache_v = (const float*)d_in[6];
    const int*   sp      = (const int*)d_in[7];
    float* out = (float*)d_out;

    cudaFuncSetAttribute(qkv_kernel,  cudaFuncAttributeMaxDynamicSharedMemorySize, G16_SMEM_BYTES);
    cudaFuncSetAttribute(out_kernel,  cudaFuncAttributeMaxDynamicSharedMemorySize, G16_SMEM_BYTES);
    cudaFuncSetAttribute(attn_kernel, cudaFuncAttributeMaxDynamicSharedMemorySize, ATTN_SMEM_BYTES);

    rope_tab_kernel<<<1, 1024>>>(sp);
    qkv_kernel<<<dim3(2, 48, KS), 256, G16_SMEM_BYTES>>>(x, Wq, Wk, Wv);
    qkv_combine_kernel<<<(MROWS * NC / 2) / 256, 256>>>();
    attn_kernel<<<128, 512, ATTN_SMEM_BYTES>>>(cache_k, cache_v, sp);
    out_kernel<<<dim3(2, 32, KS), 256, G16_SMEM_BYTES>>>(Wo);
    out_combine_kernel<<<(MROWS * D_ / 4) / 256, 256>>>(out);
}